// round 7
// baseline (speedup 1.0000x reference)
#include <cuda_runtime.h>
#include <float.h>

#define BN 4096
#define KN 32768
#define DN 128
#define HN 3
#define NSPLIT 32
#define MT 128
#define KT 256
#define DC 32
#define NT 512               // threads per CTA
#define ASTRIDE 133          // A smem row stride (floats)
#define BSTRIDE 260          // B smem row stride (floats, mult of 4 for LDS.128)

// scratch (no allocations allowed)
__device__ float g_resid[BN * DN];
__device__ float g_quant[BN * DN];
__device__ float g_rnorm[BN];               // ||r||^2 per row (XLA-order fp32)
__device__ float g_wnorm[HN * KN];          // ||w||^2 per code row (XLA-order fp32)
__device__ float g_pbv[BN * NSPLIT];
__device__ int   g_pbi[BN * NSPLIT];
__device__ int   g_codes[BN * HN];

// Packed dual fp32 FMA. Each half is an independent IEEE fp32 FMA — bitwise
// identical to scalar __fmaf_rn, so k-ascending chain semantics are unchanged.
__device__ __forceinline__ void ffma2(unsigned long long& d,
                                      unsigned long long a,
                                      unsigned long long b) {
    asm("fma.rn.f32x2 %0, %1, %2, %3;" : "=l"(d) : "l"(a), "l"(b), "l"(d));
}
__device__ __forceinline__ unsigned long long splat2(float v) {
    unsigned long long r; unsigned u = __float_as_uint(v);
    asm("mov.b64 %0, {%1, %1};" : "=l"(r) : "r"(u));
    return r;
}
__device__ __forceinline__ unsigned long long pack2(float x, float y) {
    unsigned long long r;
    asm("mov.b64 %0, {%1, %2};" : "=l"(r) : "r"(__float_as_uint(x)), "r"(__float_as_uint(y)));
    return r;
}

// ---------------------------------------------------------------------------
// XLA-style row reduction of sum(x*x): separate mul/add roundings + shfl tree.
__device__ __forceinline__ float row_sumsq_xla(const float* __restrict__ x, int lane) {
    float acc = 0.0f;
    #pragma unroll
    for (int i = 0; i < 4; i++) {
        float v = x[lane + 32 * i];
        acc = __fadd_rn(acc, __fmul_rn(v, v));
    }
    #pragma unroll
    for (int o = 16; o; o >>= 1)
        acc = __fadd_rn(acc, __shfl_down_sync(0xffffffffu, acc, o));
    return acc;
}

__global__ void wnorm_kernel(const float* __restrict__ emb) {
    int row  = blockIdx.x * 8 + (threadIdx.x >> 5);
    int lane = threadIdx.x & 31;
    if (row >= HN * KN) return;
    float s = row_sumsq_xla(emb + (size_t)row * DN, lane);
    if (lane == 0) g_wnorm[row] = s;
}

__global__ void rnorm_kernel() {
    int row  = blockIdx.x * 8 + (threadIdx.x >> 5);
    int lane = threadIdx.x & 31;
    if (row >= BN) return;
    float s = row_sumsq_xla(g_resid + (size_t)row * DN, lane);
    if (lane == 0) g_rnorm[row] = s;
}

// ---------------------------------------------------------------------------
__global__ void init_kernel(const float* __restrict__ in) {
    int i = blockIdx.x * blockDim.x + threadIdx.x;
    if (i < BN * DN) { g_resid[i] = in[i]; g_quant[i] = 0.0f; }
}

// ---------------------------------------------------------------------------
// 128-row x 256-code tile GEMM, packed FFMA2, 512 threads (4 rows x 16 codes
// per thread -> 4 warps/SMSP to hide LDS latency).
// A (resid tile) preloaded ONCE per CTA, scalar [d][row], splatted at use.
// B chunked 32-d at a time, q-interleaved so each thread's 16 codes are read
// as 4 conflict-free LDS.128.
// Score replicates reference rounding: s = fsub(fadd(rn,wn), 2*dot); argmin,
// strict < => lowest code index.
__global__ __launch_bounds__(NT)
void argmax_kernel(const float* __restrict__ emb, int h) {
    extern __shared__ float smem[];
    float* Asc = smem;                       // [DN][ASTRIDE]
    float* Bs  = smem + DN * ASTRIDE;        // [DC][BSTRIDE]

    const float* W  = emb + (size_t)h * KN * DN;
    const float* wn = g_wnorm + h * KN;

    const int mBase      = blockIdx.x * MT;
    const int kSplit     = KN / NSPLIT;          // 1024
    const int kSplitBase = blockIdx.y * kSplit;
    const int tid = threadIdx.x;
    const int tx = tid & 15, ty = tid >> 4;      // ty: 0..31

    // ---- preload A (all 128 d) once ----
    #pragma unroll
    for (int it = 0; it < 8; it++) {
        int item = tid + NT * it;            // 0..4095
        int r  = item >> 5;                  // 0..127
        int d4 = item & 31;                  // 0..31
        float4 va = *(const float4*)&g_resid[(size_t)(mBase + r) * DN + d4 * 4];
        Asc[(d4 * 4 + 0) * ASTRIDE + r] = va.x;
        Asc[(d4 * 4 + 1) * ASTRIDE + r] = va.y;
        Asc[(d4 * 4 + 2) * ASTRIDE + r] = va.z;
        Asc[(d4 * 4 + 3) * ASTRIDE + r] = va.w;
    }

    float bestv[4];
    int   besti[4];
    #pragma unroll
    for (int i = 0; i < 4; i++) { bestv[i] = FLT_MAX; besti[i] = 0; }

    float rn[4];
    #pragma unroll
    for (int i = 0; i < 4; i++) rn[i] = g_rnorm[mBase + i * 32 + ty];

    for (int kt = 0; kt < kSplit; kt += KT) {
        const int kBase = kSplitBase + kt;

        unsigned long long acc2[4][8];   // [row i][code pair p]
        #pragma unroll
        for (int i = 0; i < 4; i++)
            #pragma unroll
            for (int p = 0; p < 8; p++) acc2[i][p] = 0ull;

        for (int dc = 0; dc < DN; dc += DC) {
            __syncthreads();   // previous chunk's reads done
            // load B chunk: 256 codes x 32 d, q-interleaved columns:
            // word(c) = ((c>>2)&3)*64 + (c>>4)*4 + (c&3)
            #pragma unroll
            for (int it = 0; it < 4; it++) {
                int item = tid + NT * it;    // 0..2047
                int c  = item >> 3;          // 0..255
                int d4 = item & 7;           // 0..7
                float4 vb = *(const float4*)&W[(size_t)(kBase + c) * DN + dc + d4 * 4];
                int widx = ((c >> 2) & 3) * 64 + (c >> 4) * 4 + (c & 3);
                Bs[(d4 * 4 + 0) * BSTRIDE + widx] = vb.x;
                Bs[(d4 * 4 + 1) * BSTRIDE + widx] = vb.y;
                Bs[(d4 * 4 + 2) * BSTRIDE + widx] = vb.z;
                Bs[(d4 * 4 + 3) * BSTRIDE + widx] = vb.w;
            }
            __syncthreads();

            #pragma unroll 8
            for (int dd = 0; dd < DC; dd++) {
                const int d = dc + dd;
                unsigned long long a2[4];
                #pragma unroll
                for (int i = 0; i < 4; i++)
                    a2[i] = splat2(Asc[d * ASTRIDE + i * 32 + ty]);
                unsigned long long b2[8];
                #pragma unroll
                for (int q = 0; q < 4; q++) {
                    float4 f = *(const float4*)&Bs[dd * BSTRIDE + q * 64 + tx * 4];
                    b2[q * 2 + 0] = pack2(f.x, f.y);   // codes tx*16+q*4+{0,1}
                    b2[q * 2 + 1] = pack2(f.z, f.w);   // codes tx*16+q*4+{2,3}
                }
                #pragma unroll
                for (int i = 0; i < 4; i++)
                    #pragma unroll
                    for (int p = 0; p < 8; p++)
                        ffma2(acc2[i][p], a2[i], b2[p]);   // k-ascending chain
            }
        }

        // epilogue: reference rounding events, ascending code order
        #pragma unroll
        for (int p = 0; p < 8; p++) {
            int   kk  = kBase + tx * 16 + p * 2;
            float w2a = wn[kk];
            float w2b = wn[kk + 1];
            #pragma unroll
            for (int i = 0; i < 4; i++) {
                float dlo = __uint_as_float((unsigned)(acc2[i][p] & 0xffffffffull));
                float dhi = __uint_as_float((unsigned)(acc2[i][p] >> 32));
                float s  = __fsub_rn(__fadd_rn(rn[i], w2a), __fmul_rn(2.0f, dlo));
                if (s < bestv[i]) { bestv[i] = s; besti[i] = kk; }
                float s2 = __fsub_rn(__fadd_rn(rn[i], w2b), __fmul_rn(2.0f, dhi));
                if (s2 < bestv[i]) { bestv[i] = s2; besti[i] = kk + 1; }
            }
        }
    }

    // cross-thread reduction per row (tx lanes hold disjoint code sets)
    __syncthreads();
    float* sv = smem;                 // 2048 floats
    int*   si = (int*)(smem + 2048);  // 2048 ints
    #pragma unroll
    for (int i = 0; i < 4; i++) {
        int row = i * 32 + ty;
        sv[row * 16 + tx] = bestv[i];
        si[row * 16 + tx] = besti[i];
    }
    __syncthreads();
    if (tid < 128) {
        float bv = FLT_MAX; int bi = 0x7fffffff;
        #pragma unroll
        for (int t = 0; t < 16; t++) {
            float v = sv[tid * 16 + t]; int id = si[tid * 16 + t];
            if (v < bv || (v == bv && id < bi)) { bv = v; bi = id; }
        }
        g_pbv[(size_t)(mBase + tid) * NSPLIT + blockIdx.y] = bv;
        g_pbi[(size_t)(mBase + tid) * NSPLIT + blockIdx.y] = bi;
    }
}

// ---------------------------------------------------------------------------
__global__ void update_kernel(const float* __restrict__ emb, int h) {
    int row = blockIdx.x;     // BN blocks, 128 threads
    __shared__ int sc;
    if (threadIdx.x == 0) {
        float bv = FLT_MAX; int bi = 0x7fffffff;
        #pragma unroll
        for (int t = 0; t < NSPLIT; t++) {
            float v = g_pbv[(size_t)row * NSPLIT + t];
            int  id = g_pbi[(size_t)row * NSPLIT + t];
            if (v < bv || (v == bv && id < bi)) { bv = v; bi = id; }
        }
        g_codes[row * HN + h] = bi;
        sc = bi;
    }
    __syncthreads();
    int c = sc;
    float q = emb[(size_t)h * KN * DN + (size_t)c * DN + threadIdx.x];
    g_resid[(size_t)row * DN + threadIdx.x] = __fsub_rn(g_resid[(size_t)row * DN + threadIdx.x], q);
    g_quant[(size_t)row * DN + threadIdx.x] = __fadd_rn(g_quant[(size_t)row * DN + threadIdx.x], q);
}

// ---------------------------------------------------------------------------
__global__ void pack_kernel(float* __restrict__ out) {
    int i = blockIdx.x * blockDim.x + threadIdx.x;
    const int q0 = BN;
    const int c0 = BN + BN * DN;
    const int tot = c0 + BN * HN;
    if (i >= tot) return;
    if (i < q0)       out[i] = 0.0f;
    else if (i < c0)  out[i] = g_quant[i - q0];
    else              out[i] = (float)g_codes[i - c0];
}

// ---------------------------------------------------------------------------
extern "C" void kernel_launch(void* const* d_in, const int* in_sizes, int n_in,
                              void* d_out, int out_size) {
    const float* inputs = (const float*)d_in[0];   // (4096,1,128) fp32
    const float* emb    = (const float*)d_in[1];   // (3,32768,128) fp32
    float* out = (float*)d_out;

    const int smem_bytes = (DN * ASTRIDE + DC * BSTRIDE) * (int)sizeof(float); // ~101.4KB
    cudaFuncSetAttribute(argmax_kernel, cudaFuncAttributeMaxDynamicSharedMemorySize, smem_bytes);

    wnorm_kernel<<<(HN * KN) / 8, 256>>>(emb);
    init_kernel<<<(BN * DN + 255) / 256, 256>>>(inputs);

    for (int h = 0; h < HN; h++) {
        rnorm_kernel<<<BN / 8, 256>>>();           // XLA-order ||r||^2 of current resid
        dim3 grid(BN / MT, NSPLIT);
        argmax_kernel<<<grid, NT, smem_bytes>>>(emb, h);
        update_kernel<<<BN, 128>>>(emb, h);
    }

    const int tot = BN + BN * DN + BN * HN;
    pack_kernel<<<(tot + 255) / 256, 256>>>(out);
}

// round 10
// speedup vs baseline: 1.1134x; 1.1134x over previous
#include <cuda_runtime.h>
#include <float.h>

#define BN 4096
#define KN 32768
#define DN 128
#define HN 3
#define NSPLIT 32
#define MT 128
#define KT 256
#define DC 32
#define NT 256
#define ASTRIDE2 130         // A smem row stride (float2 units)
#define BSTRIDE 260          // B smem row stride (floats, even, mult of 4)

// scratch (no allocations allowed)
__device__ float g_resid[BN * DN];
__device__ float g_quant[BN * DN];
__device__ float g_rnorm[BN];               // ||r||^2 per row (XLA-order fp32)
__device__ float g_wnorm[HN * KN];          // ||w||^2 per code row (XLA-order fp32)
__device__ float g_pbv[BN * NSPLIT];
__device__ int   g_pbi[BN * NSPLIT];
__device__ int   g_codes[BN * HN];

// Packed dual fp32 FMA. Each half is an independent IEEE fp32 FMA — bitwise
// identical to scalar __fmaf_rn, so k-ascending chain semantics are unchanged.
__device__ __forceinline__ void ffma2(unsigned long long& d,
                                      unsigned long long a,
                                      unsigned long long b) {
    asm("fma.rn.f32x2 %0, %1, %2, %3;" : "=l"(d) : "l"(a), "l"(b), "l"(d));
}

// ---------------------------------------------------------------------------
// XLA-style row reduction of sum(x*x): separate mul/add roundings + shfl tree.
__device__ __forceinline__ float row_sumsq_xla(const float* __restrict__ x, int lane) {
    float acc = 0.0f;
    #pragma unroll
    for (int i = 0; i < 4; i++) {
        float v = x[lane + 32 * i];
        acc = __fadd_rn(acc, __fmul_rn(v, v));
    }
    #pragma unroll
    for (int o = 16; o; o >>= 1)
        acc = __fadd_rn(acc, __shfl_down_sync(0xffffffffu, acc, o));
    return acc;
}

__global__ void wnorm_kernel(const float* __restrict__ emb) {
    int row  = blockIdx.x * 8 + (threadIdx.x >> 5);
    int lane = threadIdx.x & 31;
    if (row >= HN * KN) return;
    float s = row_sumsq_xla(emb + (size_t)row * DN, lane);
    if (lane == 0) g_wnorm[row] = s;
}

__global__ void rnorm_kernel() {
    int row  = blockIdx.x * 8 + (threadIdx.x >> 5);
    int lane = threadIdx.x & 31;
    if (row >= BN) return;
    float s = row_sumsq_xla(g_resid + (size_t)row * DN, lane);
    if (lane == 0) g_rnorm[row] = s;
}

// ---------------------------------------------------------------------------
__global__ void init_kernel(const float* __restrict__ in) {
    int i = blockIdx.x * blockDim.x + threadIdx.x;
    if (i < BN * DN) { g_resid[i] = in[i]; g_quant[i] = 0.0f; }
}

// ---------------------------------------------------------------------------
// B chunk loaders: register double-buffer. Each (it,thread) owns a code PAIR
// (2p, 2p+1) and a 4-d group -> 2 LDG.128 in, 4 STS.64 out (pair-packed).
__device__ __forceinline__ void ldgB(const float* __restrict__ W, int kBase, int dc,
                                     int tid, float4* pa, float4* pb) {
    #pragma unroll
    for (int it = 0; it < 4; it++) {
        int item = tid + NT * it;            // 0..1023
        int p  = item >> 3;                  // 0..127 code pair
        int d4 = item & 7;                   // 0..7
        const float* base = W + (size_t)(kBase + 2 * p) * DN + dc + d4 * 4;
        pa[it] = *(const float4*)base;         // code 2p
        pb[it] = *(const float4*)(base + DN);  // code 2p+1
    }
}
__device__ __forceinline__ void stsB(float* __restrict__ Bs, int tid,
                                     const float4* pa, const float4* pb) {
    #pragma unroll
    for (int it = 0; it < 4; it++) {
        int item = tid + NT * it;
        int p  = item >> 3;
        int d4 = item & 7;
        int c0 = 2 * p;
        // word(c) = ((c>>2)&3)*64 + (c>>4)*4 + (c&3); widx(c0) even, widx(c0+1)=widx(c0)+1
        int widx = ((c0 >> 2) & 3) * 64 + (c0 >> 4) * 4 + (c0 & 3);
        *(float2*)&Bs[(d4 * 4 + 0) * BSTRIDE + widx] = make_float2(pa[it].x, pb[it].x);
        *(float2*)&Bs[(d4 * 4 + 1) * BSTRIDE + widx] = make_float2(pa[it].y, pb[it].y);
        *(float2*)&Bs[(d4 * 4 + 2) * BSTRIDE + widx] = make_float2(pa[it].z, pb[it].z);
        *(float2*)&Bs[(d4 * 4 + 3) * BSTRIDE + widx] = make_float2(pa[it].w, pb[it].w);
    }
}

// ---------------------------------------------------------------------------
// 128-row x 256-code tile GEMM, packed FFMA2, 256 threads, 8x16 micro-tile.
// A preloaded once, duplicated {v,v} -> direct LDS.64 operand (no splat movs).
// B pair-packed in smem -> ulonglong2 LDS.128 feeds ffma2 directly (no packs).
// B global loads register-double-buffered across chunks.
// Score replicates reference rounding: s = fsub(fadd(rn,wn), 2*dot); argmin,
// strict < => lowest code index on ties.
__global__ __launch_bounds__(NT, 1)
void argmax_kernel(const float* __restrict__ emb, int h) {
    extern __shared__ float smem[];
    float2* Asd = (float2*)smem;                   // [DN][ASTRIDE2] duplicated
    float*  Bs  = smem + DN * ASTRIDE2 * 2;        // [DC][BSTRIDE]

    const float* W  = emb + (size_t)h * KN * DN;
    const float* wn = g_wnorm + h * KN;

    const int mBase      = blockIdx.x * MT;
    const int kSplit     = KN / NSPLIT;            // 1024
    const int kSplitBase = blockIdx.y * kSplit;
    const int tid = threadIdx.x;
    const int tx = tid & 15, ty = tid >> 4;        // 16 x 16

    // ---- prefetch B chunk 0 into registers ----
    float4 pba[4], pbb[4];
    ldgB(W, kSplitBase, 0, tid, pba, pbb);

    // ---- preload A (all 128 d) once, duplicated ----
    #pragma unroll
    for (int it = 0; it < 16; it++) {
        int item = tid + NT * it;            // 0..4095
        int r  = item >> 5;                  // 0..127
        int d4 = item & 31;                  // 0..31
        float4 va = *(const float4*)&g_resid[(size_t)(mBase + r) * DN + d4 * 4];
        Asd[(d4 * 4 + 0) * ASTRIDE2 + r] = make_float2(va.x, va.x);
        Asd[(d4 * 4 + 1) * ASTRIDE2 + r] = make_float2(va.y, va.y);
        Asd[(d4 * 4 + 2) * ASTRIDE2 + r] = make_float2(va.z, va.z);
        Asd[(d4 * 4 + 3) * ASTRIDE2 + r] = make_float2(va.w, va.w);
    }

    float bestv[8];
    int   besti[8];
    #pragma unroll
    for (int i = 0; i < 8; i++) { bestv[i] = FLT_MAX; besti[i] = 0; }

    float rn[8];
    #pragma unroll
    for (int i = 0; i < 8; i++) rn[i] = g_rnorm[mBase + i * 16 + ty];

    const int NKT = kSplit / KT;    // 4
    for (int kt = 0; kt < NKT; kt++) {
        const int kBase = kSplitBase + kt * KT;

        unsigned long long acc2[8][8];   // [row i][code pair p]
        #pragma unroll
        for (int i = 0; i < 8; i++)
            #pragma unroll
            for (int p = 0; p < 8; p++) acc2[i][p] = 0ull;

        for (int ch = 0; ch < 4; ch++) {
            __syncthreads();             // previous chunk's reads done
            stsB(Bs, tid, pba, pbb);
            __syncthreads();

            int ci = kt * 4 + ch + 1;    // prefetch next chunk (overlaps compute)
            if (ci < NKT * 4)
                ldgB(W, kSplitBase + (ci >> 2) * KT, (ci & 3) * DC, tid, pba, pbb);

            #pragma unroll 8
            for (int dd = 0; dd < DC; dd++) {
                const int d = ch * DC + dd;
                unsigned long long a2[8];
                #pragma unroll
                for (int i = 0; i < 8; i++)
                    a2[i] = *(const unsigned long long*)&Asd[d * ASTRIDE2 + i * 16 + ty];
                ulonglong2 bq[4];
                #pragma unroll
                for (int q = 0; q < 4; q++)
                    bq[q] = *(const ulonglong2*)&Bs[dd * BSTRIDE + q * 64 + tx * 4];
                #pragma unroll
                for (int i = 0; i < 8; i++) {
                    #pragma unroll
                    for (int q = 0; q < 4; q++) {
                        ffma2(acc2[i][q * 2 + 0], a2[i], bq[q].x);  // k-ascending chains
                        ffma2(acc2[i][q * 2 + 1], a2[i], bq[q].y);
                    }
                }
            }
        }

        // epilogue: reference rounding events, ascending code order
        #pragma unroll
        for (int p = 0; p < 8; p++) {
            int    kk = kBase + tx * 16 + p * 2;
            float2 w2 = *(const float2*)&wn[kk];
            #pragma unroll
            for (int i = 0; i < 8; i++) {
                float dlo = __uint_as_float((unsigned)(acc2[i][p] & 0xffffffffull));
                float dhi = __uint_as_float((unsigned)(acc2[i][p] >> 32));
                float s  = __fsub_rn(__fadd_rn(rn[i], w2.x), __fmul_rn(2.0f, dlo));
                if (s < bestv[i]) { bestv[i] = s; besti[i] = kk; }
                float s2 = __fsub_rn(__fadd_rn(rn[i], w2.y), __fmul_rn(2.0f, dhi));
                if (s2 < bestv[i]) { bestv[i] = s2; besti[i] = kk + 1; }
            }
        }
    }

    // cross-thread reduction per row (tx lanes hold disjoint code sets)
    __syncthreads();
    float* sv = smem;                 // 2048 floats
    int*   si = (int*)(smem + 2048);  // 2048 ints
    #pragma unroll
    for (int i = 0; i < 8; i++) {
        int row = i * 16 + ty;
        sv[row * 16 + tx] = bestv[i];
        si[row * 16 + tx] = besti[i];
    }
    __syncthreads();
    if (tid < 128) {
        float bv = FLT_MAX; int bi = 0x7fffffff;
        #pragma unroll
        for (int t = 0; t < 16; t++) {
            float v = sv[tid * 16 + t]; int id = si[tid * 16 + t];
            if (v < bv || (v == bv && id < bi)) { bv = v; bi = id; }
        }
        g_pbv[(size_t)(mBase + tid) * NSPLIT + blockIdx.y] = bv;
        g_pbi[(size_t)(mBase + tid) * NSPLIT + blockIdx.y] = bi;
    }
}

// ---------------------------------------------------------------------------
__global__ void update_kernel(const float* __restrict__ emb, int h) {
    int row = blockIdx.x;     // BN blocks, 128 threads
    __shared__ int sc;
    if (threadIdx.x == 0) {
        float bv = FLT_MAX; int bi = 0x7fffffff;
        #pragma unroll
        for (int t = 0; t < NSPLIT; t++) {
            float v = g_pbv[(size_t)row * NSPLIT + t];
            int  id = g_pbi[(size_t)row * NSPLIT + t];
            if (v < bv || (v == bv && id < bi)) { bv = v; bi = id; }
        }
        g_codes[row * HN + h] = bi;
        sc = bi;
    }
    __syncthreads();
    int c = sc;
    float q = emb[(size_t)h * KN * DN + (size_t)c * DN + threadIdx.x];
    g_resid[(size_t)row * DN + threadIdx.x] = __fsub_rn(g_resid[(size_t)row * DN + threadIdx.x], q);
    g_quant[(size_t)row * DN + threadIdx.x] = __fadd_rn(g_quant[(size_t)row * DN + threadIdx.x], q);
}

// ---------------------------------------------------------------------------
__global__ void pack_kernel(float* __restrict__ out) {
    int i = blockIdx.x * blockDim.x + threadIdx.x;
    const int q0 = BN;
    const int c0 = BN + BN * DN;
    const int tot = c0 + BN * HN;
    if (i >= tot) return;
    if (i < q0)       out[i] = 0.0f;
    else if (i < c0)  out[i] = g_quant[i - q0];
    else              out[i] = (float)g_codes[i - c0];
}

// ---------------------------------------------------------------------------
extern "C" void kernel_launch(void* const* d_in, const int* in_sizes, int n_in,
                              void* d_out, int out_size) {
    const float* inputs = (const float*)d_in[0];   // (4096,1,128) fp32
    const float* emb    = (const float*)d_in[1];   // (3,32768,128) fp32
    float* out = (float*)d_out;

    const int smem_bytes = (DN * ASTRIDE2 * 2 + DC * BSTRIDE) * (int)sizeof(float); // 166400
    cudaFuncSetAttribute(argmax_kernel, cudaFuncAttributeMaxDynamicSharedMemorySize, smem_bytes);

    wnorm_kernel<<<(HN * KN) / 8, 256>>>(emb);
    init_kernel<<<(BN * DN + 255) / 256, 256>>>(inputs);

    for (int h = 0; h < HN; h++) {
        rnorm_kernel<<<BN / 8, 256>>>();           // XLA-order ||r||^2 of current resid
        dim3 grid(BN / MT, NSPLIT);
        argmax_kernel<<<grid, NT, smem_bytes>>>(emb, h);
        update_kernel<<<BN, 128>>>(emb, h);
    }

    const int tot = BN + BN * DN + BN * HN;
    pack_kernel<<<(tot + 255) / 256, 256>>>(out);
}